// round 2
// baseline (speedup 1.0000x reference)
#include <cuda_runtime.h>
#include <cuda_bf16.h>
#include <math.h>

#define SS 128
#define BB 1024
#define EE 256
#define HH 256
#define H3 768
#define FF 512
#define SB (SS*BB)          // 131072

// ---------------- scratch (device globals; no allocs allowed) ----------------
__device__ float g_gi[2][SB * H3];     // precomputed x@W_ih^T + b_ih, per dir (805 MB)
__device__ float g_f[SB * FF];         // f_output [S,B,2H] (256 MB)
__device__ float g_h[2][2][BB * HH];   // [pingpong][dir][B*H]
__device__ float g_scores[SB];
__device__ float g_alpha[SB];

__device__ __forceinline__ float sigmoidf_(float x) {
    return 1.0f / (1.0f + expf(-x));
}

// ---------------- h init: copy hidden_state into ping buffer 0 ----------------
__global__ void hinit_kernel(const float* __restrict__ hs) {
    int idx = blockIdx.x * blockDim.x + threadIdx.x;
    if (idx < 2 * BB * HH) {
        (&g_h[0][0][0])[idx] = hs[idx];
    }
}

// ---------------- input GEMM: gi = gather(emb,tokens) @ W_ih^T + b_ih ----------
// M=SB, N=768, K=256, NT layout. BM=64, BN=64, BK=16, 256 thr, 4x4 per thread.
__global__ __launch_bounds__(256) void gi_gemm_kernel(
    const int* __restrict__ tokens, const float* __restrict__ emb,
    const float* __restrict__ Wf, const float* __restrict__ bf,
    const float* __restrict__ Wb, const float* __restrict__ bb)
{
    const int dir = blockIdx.z;
    const float* __restrict__ W    = dir ? Wb : Wf;
    const float* __restrict__ bias = dir ? bb : bf;
    float* __restrict__ gi = g_gi[dir];

    __shared__ float As[16][68];
    __shared__ float Bs[16][68];
    __shared__ int tok_sh[64];

    const int tid = threadIdx.x;
    const int m0 = blockIdx.x * 64;
    const int n0 = blockIdx.y * 64;
    if (tid < 64) tok_sh[tid] = tokens[m0 + tid];
    __syncthreads();

    const int ty = tid >> 4, tx = tid & 15;
    const int lrow = tid >> 2, lkq = tid & 3;

    float acc[4][4] = {};

    for (int k0 = 0; k0 < EE; k0 += 16) {
        {
            const float* ap = emb + (size_t)tok_sh[lrow] * EE + k0 + lkq * 4;
            float4 v = *(const float4*)ap;
            As[lkq*4+0][lrow] = v.x; As[lkq*4+1][lrow] = v.y;
            As[lkq*4+2][lrow] = v.z; As[lkq*4+3][lrow] = v.w;
        }
        {
            const float* bp = W + (size_t)(n0 + lrow) * EE + k0 + lkq * 4;
            float4 v = *(const float4*)bp;
            Bs[lkq*4+0][lrow] = v.x; Bs[lkq*4+1][lrow] = v.y;
            Bs[lkq*4+2][lrow] = v.z; Bs[lkq*4+3][lrow] = v.w;
        }
        __syncthreads();
        #pragma unroll
        for (int kk = 0; kk < 16; kk++) {
            float a[4], b[4];
            #pragma unroll
            for (int i = 0; i < 4; i++) a[i] = As[kk][ty*4 + i];
            #pragma unroll
            for (int j = 0; j < 4; j++) b[j] = Bs[kk][tx*4 + j];
            #pragma unroll
            for (int i = 0; i < 4; i++)
                #pragma unroll
                for (int j = 0; j < 4; j++)
                    acc[i][j] += a[i] * b[j];
        }
        __syncthreads();
    }

    float4 bv = *(const float4*)(bias + n0 + tx * 4);
    #pragma unroll
    for (int i = 0; i < 4; i++) {
        int m = m0 + ty*4 + i;
        float4 o;
        o.x = acc[i][0] + bv.x; o.y = acc[i][1] + bv.y;
        o.z = acc[i][2] + bv.z; o.w = acc[i][3] + bv.w;
        *(float4*)(gi + (size_t)m * H3 + n0 + tx * 4) = o;
    }
}

// ---------------- GRU step: gh = h @ W_hh^T, fused gates ----------------------
// Per block: 64 batch rows x 96 cols = 3 gates x 32 j's. K=256.
// Thread tile 4 rows x 6 cols (= 2 complete gate triples).
__global__ __launch_bounds__(256) void gru_step_kernel(
    int s, int parity,
    const float* __restrict__ Whf, const float* __restrict__ bhf,
    const float* __restrict__ Whb, const float* __restrict__ bhb)
{
    const int dir = blockIdx.z;
    const float* __restrict__ W  = dir ? Whb : Whf;
    const float* __restrict__ bh = dir ? bhb : bhf;
    const float* __restrict__ hprev = g_h[parity][dir];
    float* __restrict__ hnext = g_h[parity ^ 1][dir];
    const float* __restrict__ gi = g_gi[dir];
    const int s_io = dir ? (SS - 1 - s) : s;   // gi row + f row for this step

    __shared__ float As[16][68];    // h tile [k][b]
    __shared__ float Bs[16][100];   // W tile [k][c], c = local col in 0..95

    const int tid = threadIdx.x;
    const int m0 = blockIdx.x * 64;
    const int j0 = blockIdx.y * 32;
    const int ty = tid >> 4, tx = tid & 15;

    float acc[4][6] = {};

    for (int k0 = 0; k0 < HH; k0 += 16) {
        {
            const int lrow = tid >> 2, lkq = tid & 3;
            const float* ap = hprev + (size_t)(m0 + lrow) * HH + k0 + lkq * 4;
            float4 v = *(const float4*)ap;
            As[lkq*4+0][lrow] = v.x; As[lkq*4+1][lrow] = v.y;
            As[lkq*4+2][lrow] = v.z; As[lkq*4+3][lrow] = v.w;
        }
        for (int i = tid; i < 384; i += 256) {   // 96 cols * 4 quads
            const int c = i >> 2, kq = i & 3;
            const int gate = c % 3, j = j0 + c / 3;
            const float* bp = W + (size_t)(gate * HH + j) * HH + k0 + kq * 4;
            float4 v = *(const float4*)bp;
            Bs[kq*4+0][c] = v.x; Bs[kq*4+1][c] = v.y;
            Bs[kq*4+2][c] = v.z; Bs[kq*4+3][c] = v.w;
        }
        __syncthreads();
        #pragma unroll
        for (int kk = 0; kk < 16; kk++) {
            float a[4], b[6];
            #pragma unroll
            for (int i = 0; i < 4; i++) a[i] = As[kk][ty*4 + i];
            #pragma unroll
            for (int j = 0; j < 6; j++) b[j] = Bs[kk][tx*6 + j];
            #pragma unroll
            for (int i = 0; i < 4; i++)
                #pragma unroll
                for (int j = 0; j < 6; j++)
                    acc[i][j] += a[i] * b[j];
        }
        __syncthreads();
    }

    // fused GRU gates + h update + f_output write
    #pragma unroll
    for (int i = 0; i < 4; i++) {
        const int b_idx = m0 + ty*4 + i;
        const size_t gbase = ((size_t)s_io * BB + b_idx) * H3;
        const size_t fbase = ((size_t)s_io * BB + b_idx) * FF + (size_t)dir * HH;
        #pragma unroll
        for (int jj = 0; jj < 2; jj++) {
            const int jg = j0 + tx*2 + jj;
            float gr = acc[i][jj*3+0] + bh[jg];
            float gz = acc[i][jj*3+1] + bh[HH + jg];
            float gn = acc[i][jj*3+2] + bh[2*HH + jg];
            float ir  = gi[gbase + jg];
            float iz  = gi[gbase + HH + jg];
            float inn = gi[gbase + 2*HH + jg];
            float r = sigmoidf_(ir + gr);
            float z = sigmoidf_(iz + gz);
            float n = tanhf(inn + r * gn);
            float ho = hprev[(size_t)b_idx * HH + jg];
            float hn = (1.0f - z) * n + z * ho;
            hnext[(size_t)b_idx * HH + jg] = hn;
            g_f[fbase + jg] = hn;
        }
    }
}

// ---------------- attention scores: tanh(tanh(f@Ww+b) @ cw) --------------------
// Per block: 64 rows, sweep n-tiles of 64 over N=512, K=512 (NN GEMM), fuse
// tanh+bias+cw-dot into the epilogue; no u materialization.
__global__ __launch_bounds__(256) void attn_score_kernel(
    const float* __restrict__ Ww, const float* __restrict__ wbias,
    const float* __restrict__ cw)
{
    __shared__ float As[16][68];
    __shared__ float Bs[16][68];
    __shared__ float red[64][17];

    const int tid = threadIdx.x;
    const int m0 = blockIdx.x * 64;
    const int ty = tid >> 4, tx = tid & 15;

    float partial[4] = {};

    for (int n0 = 0; n0 < FF; n0 += 64) {
        float acc[4][4] = {};
        for (int k0 = 0; k0 < FF; k0 += 16) {
            {
                const int lrow = tid >> 2, lkq = tid & 3;
                const float* ap = g_f + (size_t)(m0 + lrow) * FF + k0 + lkq * 4;
                float4 v = *(const float4*)ap;
                As[lkq*4+0][lrow] = v.x; As[lkq*4+1][lrow] = v.y;
                As[lkq*4+2][lrow] = v.z; As[lkq*4+3][lrow] = v.w;
            }
            {
                const int kr = tid >> 4, nq = tid & 15;   // NN: n contiguous
                const float* bp = Ww + (size_t)(k0 + kr) * FF + n0 + nq * 4;
                *(float4*)&Bs[kr][nq * 4] = *(const float4*)bp;
            }
            __syncthreads();
            #pragma unroll
            for (int kk = 0; kk < 16; kk++) {
                float a[4], b[4];
                #pragma unroll
                for (int i = 0; i < 4; i++) a[i] = As[kk][ty*4 + i];
                #pragma unroll
                for (int j = 0; j < 4; j++) b[j] = Bs[kk][tx*4 + j];
                #pragma unroll
                for (int i = 0; i < 4; i++)
                    #pragma unroll
                    for (int j = 0; j < 4; j++)
                        acc[i][j] += a[i] * b[j];
            }
            __syncthreads();
        }
        #pragma unroll
        for (int j = 0; j < 4; j++) {
            const int n = n0 + tx*4 + j;
            const float wb = wbias[n];
            const float cwn = cw[n];
            #pragma unroll
            for (int i = 0; i < 4; i++) {
                partial[i] += tanhf(acc[i][j] + wb) * cwn;
            }
        }
    }

    #pragma unroll
    for (int i = 0; i < 4; i++) red[ty*4 + i][tx] = partial[i];
    __syncthreads();
    if (tid < 64) {
        float s = 0.0f;
        #pragma unroll
        for (int t = 0; t < 16; t++) s += red[tid][t];
        g_scores[m0 + tid] = tanhf(s);
    }
}

// ---------------- softmax over seq axis (per batch column) --------------------
__global__ void softmax_kernel() {
    int b = blockIdx.x * blockDim.x + threadIdx.x;
    if (b >= BB) return;
    float mx = -1e30f;
    for (int s = 0; s < SS; s++) mx = fmaxf(mx, g_scores[s * BB + b]);
    float sum = 0.0f;
    for (int s = 0; s < SS; s++) sum += expf(g_scores[s * BB + b] - mx);
    float inv = 1.0f / sum;
    for (int s = 0; s < SS; s++)
        g_alpha[s * BB + b] = expf(g_scores[s * BB + b] - mx) * inv;
}

// ---------------- pooled = sum_s f * alpha ------------------------------------
__global__ void pool_kernel(float* __restrict__ out) {
    int idx = blockIdx.x * blockDim.x + threadIdx.x;
    if (idx >= BB * FF) return;
    int b = idx / FF;
    float acc = 0.0f;
    for (int s = 0; s < SS; s++)
        acc += g_f[((size_t)s * BB + b) * FF + (idx % FF)] * g_alpha[s * BB + b];
    out[idx] = acc;
}

// ---------------- final hidden state copy -------------------------------------
__global__ void hcopy_kernel(float* __restrict__ out) {
    int idx = blockIdx.x * blockDim.x + threadIdx.x;
    if (idx < 2 * BB * HH) {
        // after 128 steps (last step parity=1 writes buffer 0), final h is g_h[0]
        out[BB * FF + idx] = (&g_h[0][0][0])[idx];
    }
}

// ---------------- launch ------------------------------------------------------
extern "C" void kernel_launch(void* const* d_in, const int* in_sizes, int n_in,
                              void* d_out, int out_size) {
    const int*   tokens = (const int*)  d_in[0];
    const float* hidden = (const float*)d_in[1];
    const float* emb    = (const float*)d_in[2];
    const float* W_ih_f = (const float*)d_in[3];
    const float* W_hh_f = (const float*)d_in[4];
    const float* b_ih_f = (const float*)d_in[5];
    const float* b_hh_f = (const float*)d_in[6];
    const float* W_ih_b = (const float*)d_in[7];
    const float* W_hh_b = (const float*)d_in[8];
    const float* b_ih_b = (const float*)d_in[9];
    const float* b_hh_b = (const float*)d_in[10];
    const float* Ww     = (const float*)d_in[11];
    const float* wbias  = (const float*)d_in[12];
    const float* cw     = (const float*)d_in[13];
    float* out = (float*)d_out;

    hinit_kernel<<<(2 * BB * HH + 255) / 256, 256>>>(hidden);

    {
        dim3 g(SB / 64, H3 / 64, 2);
        gi_gemm_kernel<<<g, 256>>>(tokens, emb, W_ih_f, b_ih_f, W_ih_b, b_ih_b);
    }

    for (int s = 0; s < SS; s++) {
        dim3 g(BB / 64, HH / 32, 2);
        gru_step_kernel<<<g, 256>>>(s, s & 1, W_hh_f, b_hh_f, W_hh_b, b_hh_b);
    }

    attn_score_kernel<<<SB / 64, 256>>>(Ww, wbias, cw);
    softmax_kernel<<<4, 256>>>();
    pool_kernel<<<(BB * FF + 255) / 256, 256>>>(out);
    hcopy_kernel<<<(2 * BB * HH + 255) / 256, 256>>>(out);
}

// round 3
// speedup vs baseline: 2.3173x; 2.3173x over previous
#include <cuda_runtime.h>
#include <cuda_fp16.h>
#include <math.h>
#include <stdint.h>

#define SS 128
#define BB 1024
#define EE 256
#define HH 256
#define H3 768
#define FF 512
#define SB (SS*BB)          // 131072
#define VV 50000

// ---------------- device scratch (no allocs allowed) ----------------
__device__ __half g_emb16[(size_t)VV * EE];
__device__ __half g_Wih16[2][H3 * EE];
__device__ __half g_Whh16[2][H3 * HH];
__device__ __half g_WwT16[FF * FF];           // [n][k] = Ww[k][n]
__device__ float  g_gi[2][(size_t)SB * H3];
__device__ float  g_f[(size_t)SB * FF];
__device__ __half g_f16[(size_t)SB * FF];
__device__ float  g_h32[2][2][BB * HH];       // [pingpong][dir]
__device__ __half g_h16[2][2][BB * HH];
__device__ float  g_scores_pre[SB];
__device__ float  g_alpha[SB];
__device__ unsigned g_bar_cnt;
__device__ volatile unsigned g_bar_gen;

// ---------------- helpers ----------------
__device__ __forceinline__ uint32_t smem_u32(const void* p) {
    return (uint32_t)__cvta_generic_to_shared(p);
}
__device__ __forceinline__ void ldsm4(uint32_t& r0, uint32_t& r1, uint32_t& r2, uint32_t& r3, uint32_t a) {
    asm volatile("ldmatrix.sync.aligned.m8n8.x4.shared.b16 {%0,%1,%2,%3},[%4];"
                 : "=r"(r0), "=r"(r1), "=r"(r2), "=r"(r3) : "r"(a));
}
__device__ __forceinline__ void ldsm2(uint32_t& r0, uint32_t& r1, uint32_t a) {
    asm volatile("ldmatrix.sync.aligned.m8n8.x2.shared.b16 {%0,%1},[%2];"
                 : "=r"(r0), "=r"(r1) : "r"(a));
}
__device__ __forceinline__ void mma16816(float* c, uint32_t a0, uint32_t a1, uint32_t a2, uint32_t a3,
                                         uint32_t b0, uint32_t b1) {
    asm volatile("mma.sync.aligned.m16n8k16.row.col.f32.f16.f16.f32 "
                 "{%0,%1,%2,%3},{%4,%5,%6,%7},{%8,%9},{%0,%1,%2,%3};"
                 : "+f"(c[0]), "+f"(c[1]), "+f"(c[2]), "+f"(c[3])
                 : "r"(a0), "r"(a1), "r"(a2), "r"(a3), "r"(b0), "r"(b1));
}
__device__ __forceinline__ float sigmoidf_(float x) { return 1.0f / (1.0f + expf(-x)); }

#define AST 24     // A tile row stride (halves): 16 + pad
#define WST 264    // W tile row stride (halves): 256 + pad

// Ws: 96 cols (gate-blocked: c = gate*32 + jj  <->  W row gate*HH + j0 + jj), K=256
__device__ __forceinline__ void load_Ws(__half* Ws, const __half* W16, int j0, int tid) {
    for (int i = tid; i < 96 * 32; i += 256) {
        int c = i >> 5, seg = i & 31;
        int wrow = (c >> 5) * HH + j0 + (c & 31);
        uint4 v = *(const uint4*)(W16 + (size_t)wrow * 256 + seg * 8);
        *(uint4*)(Ws + c * WST + seg * 8) = v;
    }
}

// 12 mma (4 mfrag x 3 nfrag) for one 16-k chunk: A tile [128][AST], Ws full-K
__device__ __forceinline__ void mma_tile_12(const __half* Atile, const __half* Ws, int kc,
                                            int wm0, int wn0, int lane, float (&c)[4][3][4]) {
    uint32_t a[4][4];
    uint32_t abase = smem_u32(Atile + (wm0 + (lane & 15)) * AST + ((lane >> 4) << 3));
    #pragma unroll
    for (int mf = 0; mf < 4; mf++)
        ldsm4(a[mf][0], a[mf][1], a[mf][2], a[mf][3], abase + mf * (16 * AST * 2));
    uint32_t b[3][2];
    uint32_t bbase = smem_u32(Ws + (wn0 + (lane & 7)) * WST + kc + (((lane >> 3) & 1) << 3));
    #pragma unroll
    for (int nf = 0; nf < 3; nf++)
        ldsm2(b[nf][0], b[nf][1], bbase + nf * (8 * WST * 2));
    #pragma unroll
    for (int mf = 0; mf < 4; mf++)
        #pragma unroll
        for (int nf = 0; nf < 3; nf++)
            mma16816(c[mf][nf], a[mf][0], a[mf][1], a[mf][2], a[mf][3], b[nf][0], b[nf][1]);
}

// ---------------- conversions + init ----------------
__global__ void conv_main(const float* __restrict__ emb,
                          const float* __restrict__ Wihf, const float* __restrict__ Wihb,
                          const float* __restrict__ Whhf, const float* __restrict__ Whhb,
                          const float* __restrict__ Ww,   const float* __restrict__ hidden) {
    int i = blockIdx.x * blockDim.x + threadIdx.x;
    int st = gridDim.x * blockDim.x;
    for (size_t j = i; j < (size_t)VV * EE; j += st) g_emb16[j] = __float2half(emb[j]);
    for (int j = i; j < H3 * EE; j += st) {
        g_Wih16[0][j] = __float2half(Wihf[j]);
        g_Wih16[1][j] = __float2half(Wihb[j]);
        g_Whh16[0][j] = __float2half(Whhf[j]);
        g_Whh16[1][j] = __float2half(Whhb[j]);
    }
    for (int j = i; j < FF * FF; j += st) {
        int n = j / FF, k = j % FF;
        g_WwT16[j] = __float2half(Ww[(size_t)k * FF + n]);
    }
    for (int j = i; j < 2 * BB * HH; j += st) {
        float v = hidden[j];
        (&g_h32[0][0][0])[j] = v;
        (&g_h16[0][0][0])[j] = __float2half(v);
    }
    for (int j = i; j < SB; j += st) g_scores_pre[j] = 0.0f;
}

// ---------------- gi = gather(emb,tokens) @ W_ih^T + b_ih  (fp16 mma) ----------------
// grid (SB/128, 8, 2); block tile 128 x 96 (gate-blocked cols)
__global__ void __launch_bounds__(256) gi_mma(const int* __restrict__ tokens,
                                              const float* __restrict__ bif,
                                              const float* __restrict__ bib) {
    extern __shared__ unsigned char smem[];
    __half* Ws = (__half*)smem;                        // 96*WST*2 = 50688
    __half* As = (__half*)(smem + 96 * WST * 2);       // 2 * 128*AST*2 = 12288
    __shared__ int tok[128];

    const int tid = threadIdx.x, lane = tid & 31, wid = tid >> 5;
    const int m0 = blockIdx.x * 128, j0 = blockIdx.y * 32, dir = blockIdx.z;
    const int wm0 = (wid >> 2) * 64, wn0 = (wid & 3) * 24;

    load_Ws(Ws, g_Wih16[dir], j0, tid);
    if (tid < 128) tok[tid] = tokens[m0 + tid];
    __syncthreads();

    const int arow = tid >> 1, apart = tid & 1;
    const __half* esrc = g_emb16 + (size_t)tok[arow] * EE + apart * 8;
    uint4 pref = *(const uint4*)esrc;

    float c[4][3][4] = {};
    for (int t = 0; t < 16; t++) {
        *(uint4*)(As + (t & 1) * 128 * AST + arow * AST + apart * 8) = pref;
        __syncthreads();
        if (t < 15) pref = *(const uint4*)(esrc + (t + 1) * 16);
        mma_tile_12(As + (t & 1) * 128 * AST, Ws, t * 16, wm0, wn0, lane, c);
    }

    const float* bias = dir ? bib : bif;
    float* go = g_gi[dir];
    #pragma unroll
    for (int mf = 0; mf < 4; mf++) {
        const int r = m0 + wm0 + mf * 16 + (lane >> 2);
        #pragma unroll
        for (int nf = 0; nf < 3; nf++) {
            const int cc = wn0 + nf * 8 + (lane & 3) * 2;
            const int n = (cc >> 5) * HH + j0 + (cc & 31);
            float b0 = bias[n], b1 = bias[n + 1];
            float2 v0 = make_float2(c[mf][nf][0] + b0, c[mf][nf][1] + b1);
            float2 v1 = make_float2(c[mf][nf][2] + b0, c[mf][nf][3] + b1);
            *(float2*)(go + (size_t)r * H3 + n) = v0;
            *(float2*)(go + (size_t)(r + 8) * H3 + n) = v1;
        }
    }
}

// ---------------- persistent GRU (fp16 mma + global barrier) ----------------
__device__ __forceinline__ void grid_barrier() {
    __syncthreads();
    if (threadIdx.x == 0) {
        __threadfence();
        unsigned gen = g_bar_gen;
        if (atomicAdd(&g_bar_cnt, 1) == 127u) {
            atomicExch(&g_bar_cnt, 0u);
            __threadfence();
            g_bar_gen = gen + 1;
        } else {
            while (g_bar_gen == gen) {}
            __threadfence();
        }
    }
    __syncthreads();
}

__global__ void __launch_bounds__(256, 1) gru_persist(const float* __restrict__ bhf,
                                                      const float* __restrict__ bhb) {
    extern __shared__ unsigned char smem[];
    __half* Ws  = (__half*)smem;                               // 50688
    __half* As  = (__half*)(smem + 96 * WST * 2);              // 12288
    float*  Csm = (float*)(smem + 96 * WST * 2 + 2 * 128 * AST * 2); // 128*100*4 = 51200

    const int tid = threadIdx.x, lane = tid & 31, wid = tid >> 5;
    const int bid = blockIdx.x;
    const int dir = bid >> 6, mt = (bid >> 3) & 7, jt = bid & 7;
    const int m0 = mt * 128, j0 = jt * 32;
    const int wm0 = (wid >> 2) * 64, wn0 = (wid & 3) * 24;

    load_Ws(Ws, g_Whh16[dir], j0, tid);
    const float* bh = dir ? bhb : bhf;
    const float* gi = g_gi[dir];
    __syncthreads();

    const int arow = tid >> 1, apart = tid & 1;

    for (int s = 0; s < SS; s++) {
        const int par = s & 1;
        const __half* h16 = g_h16[par][dir];
        const float*  h32 = g_h32[par][dir];
        float*  hn32 = g_h32[par ^ 1][dir];
        __half* hn16 = g_h16[par ^ 1][dir];
        const int s_io = dir ? (SS - 1 - s) : s;

        const __half* hsrc = h16 + (size_t)(m0 + arow) * HH + apart * 8;
        uint4 pref = *(const uint4*)hsrc;

        float c[4][3][4] = {};
        for (int t = 0; t < 16; t++) {
            *(uint4*)(As + (t & 1) * 128 * AST + arow * AST + apart * 8) = pref;
            __syncthreads();
            if (t < 15) pref = *(const uint4*)(hsrc + (t + 1) * 16);
            mma_tile_12(As + (t & 1) * 128 * AST, Ws, t * 16, wm0, wn0, lane, c);
        }

        // frags -> smem C (so each thread can own complete gate triples)
        #pragma unroll
        for (int mf = 0; mf < 4; mf++) {
            const int r = wm0 + mf * 16 + (lane >> 2);
            #pragma unroll
            for (int nf = 0; nf < 3; nf++) {
                const int cc = wn0 + nf * 8 + (lane & 3) * 2;
                Csm[r * 100 + cc]           = c[mf][nf][0];
                Csm[r * 100 + cc + 1]       = c[mf][nf][1];
                Csm[(r + 8) * 100 + cc]     = c[mf][nf][2];
                Csm[(r + 8) * 100 + cc + 1] = c[mf][nf][3];
            }
        }
        __syncthreads();

        // gate math: 128 rows x 32 j's = 4096 triples / 256 threads
        #pragma unroll
        for (int i = 0; i < 16; i++) {
            const int idx = tid + i * 256;
            const int row = idx >> 5, jj = idx & 31;
            const int b_idx = m0 + row, jg = j0 + jj;
            const float gr = Csm[row * 100 + jj]      + bh[jg];
            const float gz = Csm[row * 100 + 32 + jj] + bh[HH + jg];
            const float gn = Csm[row * 100 + 64 + jj] + bh[2 * HH + jg];
            const size_t gb = ((size_t)s_io * BB + b_idx) * H3;
            const float ir = gi[gb + jg], iz = gi[gb + HH + jg], inn = gi[gb + 2 * HH + jg];
            const float rr = sigmoidf_(ir + gr);
            const float zz = sigmoidf_(iz + gz);
            const float nn = tanhf(inn + rr * gn);
            const float ho = h32[(size_t)b_idx * HH + jg];
            const float hv = (1.0f - zz) * nn + zz * ho;
            hn32[(size_t)b_idx * HH + jg] = hv;
            hn16[(size_t)b_idx * HH + jg] = __float2half(hv);
            const size_t fb = ((size_t)s_io * BB + b_idx) * FF + (size_t)dir * HH + jg;
            g_f[fb] = hv;
            g_f16[fb] = __float2half(hv);
        }
        __threadfence();
        grid_barrier();
    }
}

// ---------------- attention scores (fp16 mma, atomic n-reduction) ----------------
// grid (SB/128, FF/64); block tile 128 x 64; warp 64 x 16 (4 mfrag x 2 nfrag)
__global__ void __launch_bounds__(256) attn_mma(const float* __restrict__ wbias,
                                                const float* __restrict__ cw) {
    __shared__ __half As[2][128 * AST];
    __shared__ __half Bs[2][64 * AST];
    __shared__ float part[128];

    const int tid = threadIdx.x, lane = tid & 31, wid = tid >> 5;
    const int m0 = blockIdx.x * 128, n0 = blockIdx.y * 64;
    const int wm0 = (wid >> 2) * 64, wn0 = (wid & 3) * 16;

    if (tid < 128) part[tid] = 0.0f;

    const int arow = tid >> 1, apart = tid & 1;
    const __half* asrc = g_f16 + (size_t)(m0 + arow) * FF + apart * 8;
    const __half* bsrc = g_WwT16 + (size_t)(n0 + arow) * FF + apart * 8;  // rows 0..63 (tid<128)
    uint4 prefA = *(const uint4*)asrc;
    uint4 prefB = make_uint4(0, 0, 0, 0);
    if (tid < 128) prefB = *(const uint4*)bsrc;

    float c[4][2][4] = {};
    __syncthreads();

    for (int t = 0; t < 32; t++) {
        *(uint4*)(As[t & 1] + arow * AST + apart * 8) = prefA;
        if (tid < 128) *(uint4*)(Bs[t & 1] + arow * AST + apart * 8) = prefB;
        __syncthreads();
        if (t < 31) {
            prefA = *(const uint4*)(asrc + (t + 1) * 16);
            if (tid < 128) prefB = *(const uint4*)(bsrc + (t + 1) * 16);
        }
        uint32_t a[4][4];
        uint32_t abase = smem_u32(As[t & 1] + (wm0 + (lane & 15)) * AST + ((lane >> 4) << 3));
        #pragma unroll
        for (int mf = 0; mf < 4; mf++)
            ldsm4(a[mf][0], a[mf][1], a[mf][2], a[mf][3], abase + mf * (16 * AST * 2));
        uint32_t b[2][2];
        uint32_t bbase = smem_u32(Bs[t & 1] + (wn0 + (lane & 7)) * AST + (((lane >> 3) & 1) << 3));
        #pragma unroll
        for (int nf = 0; nf < 2; nf++)
            ldsm2(b[nf][0], b[nf][1], bbase + nf * (8 * AST * 2));
        #pragma unroll
        for (int mf = 0; mf < 4; mf++)
            #pragma unroll
            for (int nf = 0; nf < 2; nf++)
                mma16816(c[mf][nf], a[mf][0], a[mf][1], a[mf][2], a[mf][3], b[nf][0], b[nf][1]);
    }

    #pragma unroll
    for (int mf = 0; mf < 4; mf++) {
        const int r = wm0 + mf * 16 + (lane >> 2);
        float v0 = 0.0f, v1 = 0.0f;
        #pragma unroll
        for (int nf = 0; nf < 2; nf++) {
            const int n = n0 + wn0 + nf * 8 + (lane & 3) * 2;
            const float wb0 = wbias[n], wb1 = wbias[n + 1];
            const float c0 = cw[n], c1 = cw[n + 1];
            v0 += tanhf(c[mf][nf][0] + wb0) * c0 + tanhf(c[mf][nf][1] + wb1) * c1;
            v1 += tanhf(c[mf][nf][2] + wb0) * c0 + tanhf(c[mf][nf][3] + wb1) * c1;
        }
        atomicAdd(&part[r], v0);
        atomicAdd(&part[r + 8], v1);
    }
    __syncthreads();
    if (tid < 128) atomicAdd(&g_scores_pre[m0 + tid], part[tid]);
}

// ---------------- softmax over seq (tanh applied inline) ----------------
__global__ void softmax_kernel() {
    int b = blockIdx.x * blockDim.x + threadIdx.x;
    if (b >= BB) return;
    float mx = -1e30f;
    for (int s = 0; s < SS; s++) mx = fmaxf(mx, tanhf(g_scores_pre[s * BB + b]));
    float sum = 0.0f;
    for (int s = 0; s < SS; s++) sum += expf(tanhf(g_scores_pre[s * BB + b]) - mx);
    float inv = 1.0f / sum;
    for (int s = 0; s < SS; s++)
        g_alpha[s * BB + b] = expf(tanhf(g_scores_pre[s * BB + b]) - mx) * inv;
}

// ---------------- pooled + h_output ----------------
__global__ void pool_kernel(float* __restrict__ out) {
    int idx = blockIdx.x * blockDim.x + threadIdx.x;
    if (idx >= BB * FF) return;
    int b = idx / FF, e = idx % FF;
    float acc = 0.0f;
    for (int s = 0; s < SS; s++)
        acc += g_f[((size_t)s * BB + b) * FF + e] * g_alpha[s * BB + b];
    out[idx] = acc;
}

__global__ void hcopy_kernel(float* __restrict__ out) {
    int idx = blockIdx.x * blockDim.x + threadIdx.x;
    if (idx < 2 * BB * HH) out[BB * FF + idx] = (&g_h32[0][0][0])[idx];
}

// ---------------- launch ----------------
extern "C" void kernel_launch(void* const* d_in, const int* in_sizes, int n_in,
                              void* d_out, int out_size) {
    const int*   tokens = (const int*)  d_in[0];
    const float* hidden = (const float*)d_in[1];
    const float* emb    = (const float*)d_in[2];
    const float* W_ih_f = (const float*)d_in[3];
    const float* W_hh_f = (const float*)d_in[4];
    const float* b_ih_f = (const float*)d_in[5];
    const float* b_hh_f = (const float*)d_in[6];
    const float* W_ih_b = (const float*)d_in[7];
    const float* W_hh_b = (const float*)d_in[8];
    const float* b_ih_b = (const float*)d_in[9];
    const float* b_hh_b = (const float*)d_in[10];
    const float* Ww     = (const float*)d_in[11];
    const float* wbias  = (const float*)d_in[12];
    const float* cw     = (const float*)d_in[13];
    float* out = (float*)d_out;

    const int GI_SMEM  = 96 * WST * 2 + 2 * 128 * AST * 2;              // 62976
    const int GRU_SMEM = 96 * WST * 2 + 2 * 128 * AST * 2 + 128 * 100 * 4; // 114176
    cudaFuncSetAttribute(gi_mma,      cudaFuncAttributeMaxDynamicSharedMemorySize, GI_SMEM);
    cudaFuncSetAttribute(gru_persist, cudaFuncAttributeMaxDynamicSharedMemorySize, GRU_SMEM);

    conv_main<<<1024, 256>>>(emb, W_ih_f, W_ih_b, W_hh_f, W_hh_b, Ww, hidden);

    {
        dim3 g(SB / 128, 8, 2);
        gi_mma<<<g, 256, GI_SMEM>>>(tokens, b_ih_f, b_ih_b);
    }

    gru_persist<<<128, 256, GRU_SMEM>>>(b_hh_f, b_hh_b);

    {
        dim3 g(SB / 128, FF / 64);
        attn_mma<<<g, 256>>>(wbias, cw);
    }

    softmax_kernel<<<4, 256>>>();
    pool_kernel<<<(BB * FF + 255) / 256, 256>>>(out);
    hcopy_kernel<<<(2 * BB * HH + 255) / 256, 256>>>(out);
}

// round 5
// speedup vs baseline: 3.6849x; 1.5902x over previous
#include <cuda_runtime.h>
#include <cuda_fp16.h>
#include <math.h>
#include <stdint.h>

#define SS 128
#define BB 1024
#define EE 256
#define HH 256
#define H3 768
#define FF 512
#define SB (SS*BB)          // 131072
#define VV 50000

#define AST 24     // chunk-tile row stride (halves): 16 + pad
#define WST 264    // full-K tile row stride (halves): 256 + pad

// ---------------- device scratch (no allocs allowed) ----------------
__device__ __half g_emb16[(size_t)VV * EE];
__device__ __half g_Wih16[2][H3 * EE];
__device__ __half g_Whh16[2][H3 * HH];
__device__ __half g_WwT16[FF * FF];           // [n][k] = Ww[k][n]
__device__ __half g_gi16[2][(size_t)SB * H3];
__device__ __half g_f16[(size_t)SB * FF];
__device__ float  g_h32[2][2][BB * HH];       // [pingpong][dir]
__device__ __half g_h16[2][2][BB * HH];
__device__ float  g_scores_pre[SB];
__device__ float  g_alpha[SB];
__device__ unsigned g_gcnt[16 * 32];          // per-group barrier counters (128B apart)
__device__ volatile unsigned g_ggen[16 * 32];

// ---------------- helpers ----------------
__device__ __forceinline__ uint32_t smem_u32(const void* p) {
    return (uint32_t)__cvta_generic_to_shared(p);
}
__device__ __forceinline__ void ldsm4(uint32_t& r0, uint32_t& r1, uint32_t& r2, uint32_t& r3, uint32_t a) {
    asm volatile("ldmatrix.sync.aligned.m8n8.x4.shared.b16 {%0,%1,%2,%3},[%4];"
                 : "=r"(r0), "=r"(r1), "=r"(r2), "=r"(r3) : "r"(a));
}
__device__ __forceinline__ void mma16816(float* c, const uint32_t* a, uint32_t b0, uint32_t b1) {
    asm volatile("mma.sync.aligned.m16n8k16.row.col.f32.f16.f16.f32 "
                 "{%0,%1,%2,%3},{%4,%5,%6,%7},{%8,%9},{%0,%1,%2,%3};"
                 : "+f"(c[0]), "+f"(c[1]), "+f"(c[2]), "+f"(c[3])
                 : "r"(a[0]), "r"(a[1]), "r"(a[2]), "r"(a[3]), "r"(b0), "r"(b1));
}
__device__ __forceinline__ float sigmoidf_(float x) { return 1.0f / (1.0f + expf(-x)); }

// Ws: 96 cols, K=256 full, gate/j interleaved so mma frags hold complete triples.
// col c: wslot=c/48, cl=c%48, nf=cl/8, q=cl&7, gate=nf%3, grp=nf/3
//   -> W row = gate*HH + j0 + wslot*16 + grp*8 + q
__device__ __forceinline__ void load_Ws(__half* Ws, const __half* W16, int j0, int tid) {
    for (int i = tid; i < 96 * 32; i += 256) {
        const int c = i >> 5, seg = i & 31;
        const int wslot = c / 48, cl = c % 48, nf = cl >> 3, q = cl & 7;
        const int gate = nf % 3, grp = nf / 3;
        const int wrow = gate * HH + j0 + wslot * 16 + grp * 8 + q;
        uint4 v = *(const uint4*)(W16 + (size_t)wrow * 256 + seg * 8);
        *(uint4*)(Ws + c * WST + seg * 8) = v;
    }
}

// warp tile 32x48 (mf=2, nf=6), one k=16 chunk. 2 ldsm4(A) + 3 ldsm4(B) -> 12 mma.
template<int STRIDE>
__device__ __forceinline__ void mma_chunk_32x48(const __half* Atile, const __half* Ws,
                                                int kcA, int kcW, int wm0, int wn0c,
                                                int lane, float (&c)[2][6][4]) {
    uint32_t a[2][4];
    #pragma unroll
    for (int mf = 0; mf < 2; mf++) {
        uint32_t addr = smem_u32(Atile + (wm0 + mf * 16 + (lane & 15)) * STRIDE + kcA + ((lane >> 4) << 3));
        ldsm4(a[mf][0], a[mf][1], a[mf][2], a[mf][3], addr);
    }
    uint32_t b[6][2];
    #pragma unroll
    for (int p = 0; p < 3; p++) {
        uint32_t addr = smem_u32(Ws + (wn0c + p * 16 + (lane & 15)) * WST + kcW + ((lane >> 4) << 3));
        uint32_t r0, r1, r2, r3;
        ldsm4(r0, r1, r2, r3, addr);
        b[2*p][0] = r0; b[2*p+1][0] = r1; b[2*p][1] = r2; b[2*p+1][1] = r3;
    }
    #pragma unroll
    for (int mf = 0; mf < 2; mf++)
        #pragma unroll
        for (int nf = 0; nf < 6; nf++)
            mma16816(c[mf][nf], a[mf], b[nf][0], b[nf][1]);
}

// ---------------- conversions + init ----------------
__global__ void conv_main(const float* __restrict__ emb,
                          const float* __restrict__ Wihf, const float* __restrict__ Wihb,
                          const float* __restrict__ Whhf, const float* __restrict__ Whhb,
                          const float* __restrict__ Ww,   const float* __restrict__ hidden) {
    int i = blockIdx.x * blockDim.x + threadIdx.x;
    int st = gridDim.x * blockDim.x;
    for (size_t j = i; j < (size_t)VV * EE; j += st) g_emb16[j] = __float2half(emb[j]);
    for (int j = i; j < H3 * EE; j += st) {
        g_Wih16[0][j] = __float2half(Wihf[j]);
        g_Wih16[1][j] = __float2half(Wihb[j]);
        g_Whh16[0][j] = __float2half(Whhf[j]);
        g_Whh16[1][j] = __float2half(Whhb[j]);
    }
    for (int j = i; j < FF * FF; j += st) {
        int n = j / FF, k = j % FF;
        g_WwT16[j] = __float2half(Ww[(size_t)k * FF + n]);
    }
    for (int j = i; j < 2 * BB * HH; j += st) {
        float v = hidden[j];
        (&g_h32[0][0][0])[j] = v;
        (&g_h16[0][0][0])[j] = __float2half(v);
    }
    for (int j = i; j < SB; j += st) g_scores_pre[j] = 0.0f;
    if (i < 16 * 32) { g_gcnt[i] = 0u; }
}

// ---------------- gi = gather(emb,tokens) @ W_ih^T + b_ih  (fp16 out) ----------------
// grid (SB/128, 8, 2); block tile 128 x 96 (gate/j interleaved cols)
__global__ void __launch_bounds__(256) gi_mma(const int* __restrict__ tokens,
                                              const float* __restrict__ bif,
                                              const float* __restrict__ bib) {
    extern __shared__ unsigned char smem[];
    __half* Ws = (__half*)smem;                        // 96*WST*2 = 50688
    __half* As = (__half*)(smem + 96 * WST * 2);       // 2 * 128*AST*2 = 12288
    __shared__ int tok[128];

    const int tid = threadIdx.x, lane = tid & 31, wid = tid >> 5;
    const int m0 = blockIdx.x * 128, j0 = blockIdx.y * 32, dir = blockIdx.z;
    const int wm0 = (wid >> 1) * 32, wn0c = (wid & 1) * 48;

    load_Ws(Ws, g_Wih16[dir], j0, tid);
    if (tid < 128) tok[tid] = tokens[m0 + tid];
    __syncthreads();

    const int arow = tid >> 1, apart = tid & 1;
    const __half* esrc = g_emb16 + (size_t)tok[arow] * EE + apart * 8;
    uint4 pref = *(const uint4*)esrc;

    float c[2][6][4] = {};
    for (int t = 0; t < 16; t++) {
        *(uint4*)(As + (t & 1) * 128 * AST + arow * AST + apart * 8) = pref;
        __syncthreads();
        if (t < 15) pref = *(const uint4*)(esrc + (t + 1) * 16);
        mma_chunk_32x48<AST>(As + (t & 1) * 128 * AST, Ws, 0, t * 16, wm0, wn0c, lane, c);
    }

    const float* bias = dir ? bib : bif;
    __half* go = g_gi16[dir];
    const int jbase = j0 + (wid & 1) * 16 + (lane & 3) * 2;
    #pragma unroll
    for (int mf = 0; mf < 2; mf++) {
        const int r0 = m0 + wm0 + mf * 16 + (lane >> 2);
        #pragma unroll
        for (int nf = 0; nf < 6; nf++) {
            const int gate = nf % 3, grp = nf / 3;
            const int n = gate * HH + jbase + grp * 8;
            const float b0 = bias[n], b1 = bias[n + 1];
            *(__half2*)(go + (size_t)r0 * H3 + n) =
                __floats2half2_rn(c[mf][nf][0] + b0, c[mf][nf][1] + b1);
            *(__half2*)(go + (size_t)(r0 + 8) * H3 + n) =
                __floats2half2_rn(c[mf][nf][2] + b0, c[mf][nf][3] + b1);
        }
    }
}

// ---------------- persistent GRU ----------------
// 128 blocks: dir(2) x mt(8) x jt(8). Group barrier over the 8 jt-blocks
// sharing (dir, mt) — the only blocks whose h rows interact.
__device__ __forceinline__ void group_barrier(int g) {
    __syncthreads();
    if (threadIdx.x == 0) {
        __threadfence();
        const int gi = g * 32;
        unsigned gen = g_ggen[gi];
        if (atomicAdd(&g_gcnt[gi], 1u) == 7u) {
            atomicExch(&g_gcnt[gi], 0u);
            __threadfence();
            g_ggen[gi] = gen + 1u;
        } else {
            while (g_ggen[gi] == gen) { __nanosleep(32); }
            __threadfence();
        }
    }
    __syncthreads();
}

__global__ void __launch_bounds__(256, 1) gru_persist(const float* __restrict__ bhf,
                                                      const float* __restrict__ bhb) {
    extern __shared__ unsigned char smem[];
    __half* Ws = (__half*)smem;                        // 50688
    __half* Ah = (__half*)(smem + 96 * WST * 2);       // 128*264*2 = 67584

    const int tid = threadIdx.x, lane = tid & 31, wid = tid >> 5;
    const int bid = blockIdx.x;
    const int dir = bid >> 6, mt = (bid >> 3) & 7, jt = bid & 7;
    const int grp_id = dir * 8 + mt;
    const int m0 = mt * 128, j0 = jt * 32;
    const int wm0 = (wid >> 1) * 32, wn0c = (wid & 1) * 48;

    load_Ws(Ws, g_Whh16[dir], j0, tid);
    const float* bh = dir ? bhb : bhf;
    const __half* gi = g_gi16[dir];
    __syncthreads();

    const int srow = tid >> 1;                 // staging helpers (row pairs)
    const int jbase = j0 + (wid & 1) * 16 + (lane & 3) * 2;

    for (int s = 0; s < SS; s++) {
        const int par = s & 1;
        const __half* h16 = g_h16[par][dir];
        const float*  h32 = g_h32[par][dir];
        float*  hn32 = g_h32[par ^ 1][dir];
        __half* hn16 = g_h16[par ^ 1][dir];
        const int s_io = dir ? (SS - 1 - s) : s;

        // stage full h tile: 128 rows x 256 halves
        #pragma unroll
        for (int i = 0; i < 16; i++) {
            const int idx = tid + i * 256;
            const int row = idx >> 5, seg = idx & 31;
            *(uint4*)(Ah + row * WST + seg * 8) =
                *(const uint4*)(h16 + (size_t)(m0 + row) * HH + seg * 8);
        }
        __syncthreads();

        float c[2][6][4] = {};
        #pragma unroll
        for (int t = 0; t < 16; t++)
            mma_chunk_32x48<WST>(Ah, Ws, t * 16, t * 16, wm0, wn0c, lane, c);

        // gate math directly on fragments (each thread owns complete triples)
        #pragma unroll
        for (int mf = 0; mf < 2; mf++) {
            const int rb = m0 + wm0 + mf * 16 + (lane >> 2);
            #pragma unroll
            for (int g = 0; g < 2; g++) {
                const int j = jbase + g * 8;
                const float bhr = bh[j],          bhr1 = bh[j + 1];
                const float bhz = bh[HH + j],     bhz1 = bh[HH + j + 1];
                const float bhn = bh[2*HH + j],   bhn1 = bh[2*HH + j + 1];
                #pragma unroll
                for (int rh = 0; rh < 2; rh++) {
                    const int row = rb + rh * 8;
                    const int e = rh * 2;
                    const size_t gb = ((size_t)s_io * BB + row) * H3;
                    const __half2 ih_r = *(const __half2*)(gi + gb + j);
                    const __half2 ih_z = *(const __half2*)(gi + gb + HH + j);
                    const __half2 ih_n = *(const __half2*)(gi + gb + 2*HH + j);
                    const float2 ir = __half22float2(ih_r);
                    const float2 iz = __half22float2(ih_z);
                    const float2 inn = __half22float2(ih_n);
                    const float2 ho = *(const float2*)(h32 + (size_t)row * HH + j);

                    const float r0 = sigmoidf_(ir.x + c[mf][3*g+0][e]   + bhr);
                    const float r1 = sigmoidf_(ir.y + c[mf][3*g+0][e+1] + bhr1);
                    const float z0 = sigmoidf_(iz.x + c[mf][3*g+1][e]   + bhz);
                    const float z1 = sigmoidf_(iz.y + c[mf][3*g+1][e+1] + bhz1);
                    const float n0 = tanhf(inn.x + r0 * (c[mf][3*g+2][e]   + bhn));
                    const float n1 = tanhf(inn.y + r1 * (c[mf][3*g+2][e+1] + bhn1));
                    const float h0 = (1.0f - z0) * n0 + z0 * ho.x;
                    const float h1 = (1.0f - z1) * n1 + z1 * ho.y;

                    *(float2*)(hn32 + (size_t)row * HH + j) = make_float2(h0, h1);
                    const __half2 hh = __floats2half2_rn(h0, h1);
                    *(__half2*)(hn16 + (size_t)row * HH + j) = hh;
                    *(__half2*)(g_f16 + ((size_t)s_io * BB + row) * FF + (size_t)dir * HH + j) = hh;
                }
            }
        }
        group_barrier(grp_id);
    }
}

// ---------------- attention scores (128x128 tile, warp 64x32) ----------------
__global__ void __launch_bounds__(256) attn_mma(const float* __restrict__ wbias,
                                                const float* __restrict__ cw) {
    __shared__ __half As[2][128 * AST];
    __shared__ __half Bs[2][128 * AST];
    __shared__ float part[128];

    const int tid = threadIdx.x, lane = tid & 31, wid = tid >> 5;
    const int m0 = blockIdx.x * 128, n0 = blockIdx.y * 128;
    const int wm0 = (wid >> 2) * 64, wn0 = (wid & 3) * 32;

    if (tid < 128) part[tid] = 0.0f;

    const int arow = tid >> 1, apart = tid & 1;
    const __half* asrc = g_f16 + (size_t)(m0 + arow) * FF + apart * 8;
    const __half* bsrc = g_WwT16 + (size_t)(n0 + arow) * FF + apart * 8;
    uint4 prefA = *(const uint4*)asrc;
    uint4 prefB = *(const uint4*)bsrc;

    float c[4][4][4] = {};
    for (int t = 0; t < 32; t++) {
        *(uint4*)(As[t & 1] + arow * AST + apart * 8) = prefA;
        *(uint4*)(Bs[t & 1] + arow * AST + apart * 8) = prefB;
        __syncthreads();
        if (t < 31) {
            prefA = *(const uint4*)(asrc + (t + 1) * 16);
            prefB = *(const uint4*)(bsrc + (t + 1) * 16);
        }
        uint32_t a[4][4];
        #pragma unroll
        for (int mf = 0; mf < 4; mf++) {
            uint32_t addr = smem_u32(As[t & 1] + (wm0 + mf * 16 + (lane & 15)) * AST + ((lane >> 4) << 3));
            ldsm4(a[mf][0], a[mf][1], a[mf][2], a[mf][3], addr);
        }
        uint32_t b[4][2];
        #pragma unroll
        for (int p = 0; p < 2; p++) {
            uint32_t addr = smem_u32(Bs[t & 1] + (wn0 + p * 16 + (lane & 15)) * AST + ((lane >> 4) << 3));
            uint32_t r0, r1, r2, r3;
            ldsm4(r0, r1, r2, r3, addr);
            b[2*p][0] = r0; b[2*p+1][0] = r1; b[2*p][1] = r2; b[2*p+1][1] = r3;
        }
        #pragma unroll
        for (int mf = 0; mf < 4; mf++)
            #pragma unroll
            for (int nf = 0; nf < 4; nf++)
                mma16816(c[mf][nf], a[mf], b[nf][0], b[nf][1]);
        __syncthreads();
    }

    #pragma unroll
    for (int mf = 0; mf < 4; mf++) {
        const int r = wm0 + mf * 16 + (lane >> 2);
        float v0 = 0.0f, v1 = 0.0f;
        #pragma unroll
        for (int nf = 0; nf < 4; nf++) {
            const int n = n0 + wn0 + nf * 8 + (lane & 3) * 2;
            const float wb0 = wbias[n], wb1 = wbias[n + 1];
            const float c0 = cw[n], c1 = cw[n + 1];
            v0 += tanhf(c[mf][nf][0] + wb0) * c0 + tanhf(c[mf][nf][1] + wb1) * c1;
            v1 += tanhf(c[mf][nf][2] + wb0) * c0 + tanhf(c[mf][nf][3] + wb1) * c1;
        }
        atomicAdd(&part[r], v0);
        atomicAdd(&part[r + 8], v1);
    }
    __syncthreads();
    if (tid < 128) atomicAdd(&g_scores_pre[m0 + tid], part[tid]);
}

// ---------------- softmax over seq (tanh applied inline) ----------------
__global__ void softmax_kernel() {
    int b = blockIdx.x * blockDim.x + threadIdx.x;
    if (b >= BB) return;
    float mx = -1e30f;
    for (int s = 0; s < SS; s++) mx = fmaxf(mx, tanhf(g_scores_pre[s * BB + b]));
    float sum = 0.0f;
    for (int s = 0; s < SS; s++) sum += expf(tanhf(g_scores_pre[s * BB + b]) - mx);
    float inv = 1.0f / sum;
    for (int s = 0; s < SS; s++)
        g_alpha[s * BB + b] = expf(tanhf(g_scores_pre[s * BB + b]) - mx) * inv;
}

// ---------------- pooled + h_output ----------------
__global__ void pool_kernel(float* __restrict__ out) {
    int idx = blockIdx.x * blockDim.x + threadIdx.x;   // over BB*FF/2
    if (idx >= BB * FF / 2) return;
    const int b = idx / (FF / 2), e = (idx % (FF / 2)) * 2;
    float ax = 0.0f, ay = 0.0f;
    for (int s = 0; s < SS; s++) {
        const __half2 v = *(const __half2*)(g_f16 + ((size_t)s * BB + b) * FF + e);
        const float2 f = __half22float2(v);
        const float a = g_alpha[s * BB + b];
        ax += f.x * a; ay += f.y * a;
    }
    out[b * FF + e] = ax;
    out[b * FF + e + 1] = ay;
}

__global__ void hcopy_kernel(float* __restrict__ out) {
    int idx = blockIdx.x * blockDim.x + threadIdx.x;
    if (idx < 2 * BB * HH) out[BB * FF + idx] = (&g_h32[0][0][0])[idx];
}

// ---------------- launch ----------------
extern "C" void kernel_launch(void* const* d_in, const int* in_sizes, int n_in,
                              void* d_out, int out_size) {
    const int*   tokens = (const int*)  d_in[0];
    const float* hidden = (const float*)d_in[1];
    const float* emb    = (const float*)d_in[2];
    const float* W_ih_f = (const float*)d_in[3];
    const float* W_hh_f = (const float*)d_in[4];
    const float* b_ih_f = (const float*)d_in[5];
    const float* b_hh_f = (const float*)d_in[6];
    const float* W_ih_b = (const float*)d_in[7];
    const float* W_hh_b = (const float*)d_in[8];
    const float* b_ih_b = (const float*)d_in[9];
    const float* b_hh_b = (const float*)d_in[10];
    const float* Ww     = (const float*)d_in[11];
    const float* wbias  = (const float*)d_in[12];
    const float* cw     = (const float*)d_in[13];
    float* out = (float*)d_out;

    const int GI_SMEM  = 96 * WST * 2 + 2 * 128 * AST * 2;   // 62976
    const int GRU_SMEM = 96 * WST * 2 + 128 * WST * 2;       // 118272
    cudaFuncSetAttribute(gi_mma,      cudaFuncAttributeMaxDynamicSharedMemorySize, GI_SMEM);
    cudaFuncSetAttribute(gru_persist, cudaFuncAttributeMaxDynamicSharedMemorySize, GRU_SMEM);

    conv_main<<<1024, 256>>>(emb, W_ih_f, W_ih_b, W_hh_f, W_hh_b, Ww, hidden);

    {
        dim3 g(SB / 128, 8, 2);
        gi_mma<<<g, 256, GI_SMEM>>>(tokens, b_ih_f, b_ih_b);
    }

    gru_persist<<<128, 256, GRU_SMEM>>>(b_hh_f, b_hh_b);

    {
        dim3 g(SB / 128, FF / 128);
        attn_mma<<<g, 256>>>(wbias, cw);
    }

    softmax_kernel<<<4, 256>>>();
    pool_kernel<<<(BB * FF / 2 + 255) / 256, 256>>>(out);
    hcopy_kernel<<<(2 * BB * HH + 255) / 256, 256>>>(out);
}